// round 13
// baseline (speedup 1.0000x reference)
#include <cuda_runtime.h>
#include <cuda_fp16.h>
#include <cstdint>

#define TT    256
#define BATCH 4096
#define H1    16
#define H2    64

// ---------------------------------------------------------------------------
// Scratch
// ---------------------------------------------------------------------------
__device__ float g_out1[(size_t)TT * BATCH * H1];   // layer-1 outputs [T][B][16]
__device__ float g_h[2 * (size_t)BATCH * H2];       // final hidden per dir

// ---------------------------------------------------------------------------
// MUFU activations (EX2+RCP)
// ---------------------------------------------------------------------------
__device__ __forceinline__ float sig_mufu(float x) {
    return __fdividef(1.0f, 1.0f + __expf(-x));
}
__device__ __forceinline__ float tanh_mufu(float x) {
    return fmaf(2.0f, __fdividef(1.0f, 1.0f + __expf(-2.0f * x)), -1.0f);
}

__device__ __forceinline__ uint32_t smem_u32(const void* p) {
    uint32_t a;
    asm("{ .reg .u64 t; cvta.to.shared.u64 t, %1; cvt.u32.u64 %0, t; }" : "=r"(a) : "l"(p));
    return a;
}

#define LDSM_X4(r0, r1, r2, r3, addr) \
    asm volatile("ldmatrix.sync.aligned.m8n8.x4.shared.b16 {%0,%1,%2,%3}, [%4];" \
        : "=r"(r0), "=r"(r1), "=r"(r2), "=r"(r3) : "r"(addr))

#define MMA_F16(d, a0, a1, a2, a3, bb0, bb1) \
    asm volatile("mma.sync.aligned.m16n8k16.row.col.f32.f16.f16.f32 " \
        "{%0,%1,%2,%3}, {%4,%5,%6,%7}, {%8,%9}, {%0,%1,%2,%3};" \
        : "+f"((d)[0]), "+f"((d)[1]), "+f"((d)[2]), "+f"((d)[3]) \
        : "r"(a0), "r"(a1), "r"(a2), "r"(a3), "r"(bb0), "r"(bb1))

// fp16 split: v = hi + lo
__device__ __forceinline__ void f16_split(float v, unsigned short& hi, unsigned short& lo) {
    __half h = __float2half_rn(v);
    float rem = v - __half2float(h);
    __half l = __float2half_rn(rem);
    hi = __half_as_ushort(h);
    lo = __half_as_ushort(l);
}
__device__ __forceinline__ uint32_t f16_pair(float a, float b, uint32_t& lop) {
    unsigned short ha, la, hb, lb;
    f16_split(a, ha, la);
    f16_split(b, hb, lb);
    lop = (uint32_t)la | ((uint32_t)lb << 16);
    return (uint32_t)ha | ((uint32_t)hb << 16);
}

// ---------------------------------------------------------------------------
// Layer 2 (HMMA, fp16 3-term split): A [32 x 160] double-buffered, B [192 x 160].
//   A: [0:64) h_hi | [64:128) h_lo | [128:144) x_hi | [144:160) x_lo
//   B: [0:64) Whh_hi | [64:128) Whh_lo | [128:144) Wih_hi | [144:160) Wih_lo
// 256 threads = 8 warps: warp = (mt = wid&1: 16 rows, jq = wid>>1: 16 j's).
// 4 warps/SMSP x 2 CTAs/SM -> MMA phase of some warps overlaps MUFU epilogue
// of others (R12 had 2 warps/SMSP and the phases serialized).
// ---------------------------------------------------------------------------
#define AROW   336
#define SM_A0  0
#define SM_A1  10752                 // 32*336
#define SM_B   21504
#define SM2_TOTAL (21504 + 192 * 336)    // 86016

__global__ void __launch_bounds__(256, 2)
gru2_kernel(const float* __restrict__ w_ihf, const float* __restrict__ w_hhf,
            const float* __restrict__ b_ihf, const float* __restrict__ b_hhf,
            const float* __restrict__ w_ihb, const float* __restrict__ w_hhb,
            const float* __restrict__ b_ihb, const float* __restrict__ b_hhb) {
    extern __shared__ char sm[];
    const uint32_t smb = smem_u32(sm);
    const int tid = threadIdx.x;
    const int wid = tid >> 5;
    const int lane = tid & 31;
    const int dir = blockIdx.y;
    const int b0 = blockIdx.x * 32;

    const float* w_ih = dir ? w_ihb : w_ihf;
    const float* w_hh = dir ? w_hhb : w_hhf;
    const float* b_ih = dir ? b_ihb : b_ihf;
    const float* b_hh = dir ? b_hhb : b_hhf;

    // ---- build B ----
    for (int idx = tid; idx < 192 * 64; idx += 256) {
        int g = idx >> 6, k = idx & 63;
        unsigned short hi, lo;
        f16_split(w_hh[idx], hi, lo);
        unsigned short* row = (unsigned short*)(sm + SM_B + g * AROW);
        row[k] = hi; row[64 + k] = lo;
    }
    for (int idx = tid; idx < 192 * 16; idx += 256) {
        int g = idx >> 4, k = idx & 15;
        unsigned short hi, lo;
        f16_split(w_ih[idx], hi, lo);
        unsigned short* row = (unsigned short*)(sm + SM_B + g * AROW);
        row[128 + k] = hi; row[144 + k] = lo;
    }
    for (int g = tid; g < 192; g += 256)
        *(uint4*)(sm + SM_B + g * AROW + 320) = make_uint4(0, 0, 0, 0);

    // ---- zero A buf0 (h(0)=0) ----
    for (int idx = tid; idx < 32 * (AROW / 16); idx += 256)
        ((uint4*)(sm + SM_A0))[idx] = make_uint4(0, 0, 0, 0);
    __syncthreads();

    // ---- stage x(t0): 256 threads = 32 rows x 8 col-pairs ----
    const int xrow = tid >> 3;          // 0..31
    const int xc2  = (tid & 7) * 2;     // 0,2,...,14
    {
        int t0 = dir ? (TT - 1) : 0;
        float2 xv = *(const float2*)(g_out1 + ((size_t)t0 * BATCH + b0 + xrow) * 16 + xc2);
        uint32_t LP, HP = f16_pair(xv.x, xv.y, LP);
        char* ar = sm + SM_A0 + xrow * AROW;
        *(uint32_t*)(ar + 256 + 2 * xc2) = HP;   // x_hi at col 128+xc2
        *(uint32_t*)(ar + 288 + 2 * xc2) = LP;   // x_lo at col 144+xc2
    }

    // ---- per-warp / per-lane constants ----
    const int mt = wid & 1;             // M-tile (16 rows)
    const int jq = wid >> 1;            // j-quarter: j in [jq*16, jq*16+16)
    const int lrow = lane & 7;
    const int grp  = lane >> 3;
    const uint32_t aRowOff = (uint32_t)(mt * 16 + lrow + ((grp & 1) << 3)) * AROW
                           + (uint32_t)((grp >> 1) << 4);
    const uint32_t bOff = (uint32_t)(lrow + ((grp >> 1) << 3)) * AROW
                        + (uint32_t)((grp & 1) << 4);
    const uint32_t bBase = smb + SM_B + bOff;
    // B block-row bases for this warp's 16-j slice per gate section
    const uint32_t rowR = bBase + (uint32_t)(jq * 16) * AROW;
    const uint32_t rowZ = bBase + (uint32_t)(64 + jq * 16) * AROW;
    const uint32_t rowN = bBase + (uint32_t)(128 + jq * 16) * AROW;

    // biases (indexed by nbh half and lane col pair)
    const int cj = 2 * (lane & 3);
    float2 br[2], bz[2], bhn[2], bxn[2];
#pragma unroll
    for (int nbh = 0; nbh < 2; ++nbh) {
        int j = jq * 16 + nbh * 8 + cj;
        br[nbh]  = make_float2(b_ih[j] + b_hh[j],           b_ih[j + 1] + b_hh[j + 1]);
        bz[nbh]  = make_float2(b_ih[64 + j] + b_hh[64 + j], b_ih[65 + j] + b_hh[65 + j]);
        bhn[nbh] = make_float2(b_hh[128 + j], b_hh[129 + j]);
        bxn[nbh] = make_float2(b_ih[128 + j], b_ih[129 + j]);
    }

    float h[8];
#pragma unroll
    for (int i = 0; i < 8; ++i) h[i] = 0.0f;

    __syncthreads();

    const int row0 = mt * 16 + (lane >> 2);
    const size_t xg_base = (size_t)(b0 + xrow) * 16 + xc2;

    for (int step = 0; step < TT; ++step) {
        const uint32_t pa = smb + ((step & 1) ? SM_A1 : SM_A0);
        char* const   pn = sm + ((step & 1) ? SM_A0 : SM_A1);

        // prefetch x(t+1)
        float2 xv;
        const bool do_x = (step + 1 < TT);
        if (do_x) {
            int tn = dir ? (TT - 2 - step) : (step + 1);
            xv = *(const float2*)(g_out1 + (size_t)tn * BATCH * 16 + xg_base);
        }

        // ---- A fragments (10 LDSM) ----
        uint32_t ah[4][4], al[4][4], axh[4], axl[4];
#pragma unroll
        for (int kc = 0; kc < 4; ++kc)
            LDSM_X4(ah[kc][0], ah[kc][1], ah[kc][2], ah[kc][3], pa + aRowOff + kc * 32);
#pragma unroll
        for (int kc = 0; kc < 4; ++kc)
            LDSM_X4(al[kc][0], al[kc][1], al[kc][2], al[kc][3], pa + aRowOff + 128 + kc * 32);
        LDSM_X4(axh[0], axh[1], axh[2], axh[3], pa + aRowOff + 256);
        LDSM_X4(axl[0], axl[1], axl[2], axl[3], pa + aRowOff + 288);

        // d accumulators initialized with biases (saves epilogue adds):
        // d[0..1]=r(nbh0,1) d[2..3]=z d[4..5]=hn d[6..7]=xn
        float d[8][4];
#pragma unroll
        for (int nbh = 0; nbh < 2; ++nbh) {
            d[0 + nbh][0] = br[nbh].x;  d[0 + nbh][1] = br[nbh].y;
            d[0 + nbh][2] = br[nbh].x;  d[0 + nbh][3] = br[nbh].y;
            d[2 + nbh][0] = bz[nbh].x;  d[2 + nbh][1] = bz[nbh].y;
            d[2 + nbh][2] = bz[nbh].x;  d[2 + nbh][3] = bz[nbh].y;
            d[4 + nbh][0] = bhn[nbh].x; d[4 + nbh][1] = bhn[nbh].y;
            d[4 + nbh][2] = bhn[nbh].x; d[4 + nbh][3] = bhn[nbh].y;
            d[6 + nbh][0] = bxn[nbh].x; d[6 + nbh][1] = bxn[nbh].y;
            d[6 + nbh][2] = bxn[nbh].x; d[6 + nbh][3] = bxn[nbh].y;
        }

        // ---- MMA phase: h-part, kc-outer over 3 gate sections (6 accums hot) ----
#pragma unroll
        for (int kc = 0; kc < 4; ++kc) {
            uint32_t q0, q1, q2, q3;
#pragma unroll
            for (int g = 0; g < 3; ++g) {
                const uint32_t rowb = (g == 0) ? rowR : (g == 1) ? rowZ : rowN;
                const int ia = g * 2;
                LDSM_X4(q0, q1, q2, q3, rowb + kc * 32);            // Whh_hi
                MMA_F16(d[ia],     ah[kc][0], ah[kc][1], ah[kc][2], ah[kc][3], q0, q1);
                MMA_F16(d[ia + 1], ah[kc][0], ah[kc][1], ah[kc][2], ah[kc][3], q2, q3);
                MMA_F16(d[ia],     al[kc][0], al[kc][1], al[kc][2], al[kc][3], q0, q1);
                MMA_F16(d[ia + 1], al[kc][0], al[kc][1], al[kc][2], al[kc][3], q2, q3);
                LDSM_X4(q0, q1, q2, q3, rowb + 128 + kc * 32);      // Whh_lo
                MMA_F16(d[ia],     ah[kc][0], ah[kc][1], ah[kc][2], ah[kc][3], q0, q1);
                MMA_F16(d[ia + 1], ah[kc][0], ah[kc][1], ah[kc][2], ah[kc][3], q2, q3);
            }
        }
        // ---- x-part: r, z accumulate; n's x goes to xn accums ----
        {
            uint32_t q0, q1, q2, q3;
#pragma unroll
            for (int g = 0; g < 3; ++g) {
                const uint32_t rowb = (g == 0) ? rowR : (g == 1) ? rowZ : rowN;
                const int ia = (g < 2) ? g * 2 : 6;                 // xn for g==2
                LDSM_X4(q0, q1, q2, q3, rowb + 256);                // Wih_hi
                MMA_F16(d[ia],     axh[0], axh[1], axh[2], axh[3], q0, q1);
                MMA_F16(d[ia + 1], axh[0], axh[1], axh[2], axh[3], q2, q3);
                MMA_F16(d[ia],     axl[0], axl[1], axl[2], axl[3], q0, q1);
                MMA_F16(d[ia + 1], axl[0], axl[1], axl[2], axl[3], q2, q3);
                LDSM_X4(q0, q1, q2, q3, rowb + 288);                // Wih_lo
                MMA_F16(d[ia],     axh[0], axh[1], axh[2], axh[3], q0, q1);
                MMA_F16(d[ia + 1], axh[0], axh[1], axh[2], axh[3], q2, q3);
            }
        }

        // No mid-step barrier (epilogue writes the buffer whose readers finished
        // before the previous end-of-step barrier).

        // ---- epilogue (MUFU pipe) + h writeback ----
#pragma unroll
        for (int nbh = 0; nbh < 2; ++nbh) {
#pragma unroll
            for (int e = 0; e < 4; ++e) {
                float rg = sig_mufu(d[0 + nbh][e]);
                float zg = sig_mufu(d[2 + nbh][e]);
                float nn = tanh_mufu(fmaf(rg, d[4 + nbh][e], d[6 + nbh][e]));
                const int hi = nbh * 4 + e;
                h[hi] = fmaf(zg, h[hi] - nn, nn);
            }
#pragma unroll
            for (int rsel = 0; rsel < 2; ++rsel) {
                const int e0 = rsel * 2;
                uint32_t LP, HP = f16_pair(h[nbh * 4 + e0], h[nbh * 4 + e0 + 1], LP);
                char* ar = pn + (row0 + rsel * 8) * AROW;
                const int j = jq * 16 + nbh * 8 + cj;
                *(uint32_t*)(ar + 2 * j)       = HP;   // h_hi
                *(uint32_t*)(ar + 128 + 2 * j) = LP;   // h_lo (col 64)
            }
        }

        // stage x(t+1)
        if (do_x) {
            uint32_t LP, HP = f16_pair(xv.x, xv.y, LP);
            char* ar = pn + xrow * AROW;
            *(uint32_t*)(ar + 256 + 2 * xc2) = HP;
            *(uint32_t*)(ar + 288 + 2 * xc2) = LP;
        }
        __syncthreads();   // A(next) complete before next step's LDSMs
    }

    // final hidden -> gmem
#pragma unroll
    for (int nbh = 0; nbh < 2; ++nbh) {
#pragma unroll
        for (int rsel = 0; rsel < 2; ++rsel) {
            const int j = jq * 16 + nbh * 8 + cj;
            float* hp = g_h + ((size_t)dir * BATCH + b0 + row0 + rsel * 8) * H2 + j;
            *(float2*)hp = make_float2(h[nbh * 4 + rsel * 2], h[nbh * 4 + rsel * 2 + 1]);
        }
    }
}

// ---------------------------------------------------------------------------
// Layer 1: GRU(2 -> 16), barrier-free warp-shuffle, MUFU activations.
// ---------------------------------------------------------------------------
__global__ void __launch_bounds__(256)
gru1_kernel(const float* __restrict__ traj,
            const float* __restrict__ w_ih1,
            const float* __restrict__ w_hh1,
            const float* __restrict__ b_ih1,
            const float* __restrict__ b_hh1) {
    const int tid  = threadIdx.x;
    const int wid  = tid >> 5;
    const int lane = tid & 31;
    const int half = lane >> 4;
    const int j    = lane & 15;
    const int el   = (blockIdx.x * 8 + wid) * 2 + half;

    float whr[16], whz[16], whn[16];
#pragma unroll
    for (int k = 0; k < 16; ++k) {
        whr[k] = w_hh1[(j)      * 16 + k];
        whz[k] = w_hh1[(16 + j) * 16 + k];
        whn[k] = w_hh1[(32 + j) * 16 + k];
    }
    const float wxr0 = w_ih1[j * 2 + 0],        wxr1 = w_ih1[j * 2 + 1];
    const float wxz0 = w_ih1[(16 + j) * 2 + 0], wxz1 = w_ih1[(16 + j) * 2 + 1];
    const float wxn0 = w_ih1[(32 + j) * 2 + 0], wxn1 = w_ih1[(32 + j) * 2 + 1];
    const float br  = b_ih1[j]      + b_hh1[j];
    const float bz  = b_ih1[16 + j] + b_hh1[16 + j];
    const float bxn = b_ih1[32 + j];
    const float bhn = b_hh1[32 + j];

    const float2* xp = (const float2*)(traj + (size_t)el * TT * 2);
    float* op = g_out1 + (size_t)el * 16 + j;
    const int sbase = half << 4;

    float h = 0.0f;
    float2 xv = xp[0];
    for (int t = 0; t < TT; ++t) {
        float x0 = xv.x, x1 = xv.y;
        if (t + 1 < TT) xv = xp[t + 1];

        float ar  = fmaf(wxr1, x1, fmaf(wxr0, x0, br));
        float az  = fmaf(wxz1, x1, fmaf(wxz0, x0, bz));
        float axn = fmaf(wxn1, x1, fmaf(wxn0, x0, bxn));
        float ahn = bhn;
#pragma unroll
        for (int k = 0; k < 16; ++k) {
            float hk = __shfl_sync(0xFFFFFFFFu, h, sbase + k);
            ar  = fmaf(whr[k], hk, ar);
            az  = fmaf(whz[k], hk, az);
            ahn = fmaf(whn[k], hk, ahn);
        }
        float r = sig_mufu(ar);
        float z = sig_mufu(az);
        float n = tanh_mufu(fmaf(r, ahn, axn));
        h = fmaf(z, h - n, n);
        op[(size_t)t * BATCH * 16] = h;
    }
}

// ---------------------------------------------------------------------------
// MLP
// ---------------------------------------------------------------------------
__global__ void mlp_kernel(const float* __restrict__ W1, const float* __restrict__ b1,
                           const float* __restrict__ W2, const float* __restrict__ b2,
                           float* __restrict__ out) {
    __shared__ float s_w1t[64 * 32];
    __shared__ float s_w2t[32 * 8];
    __shared__ float s_b1[32];
    __shared__ float s_b2[8];
    __shared__ float s_m1[8 * 32];

    const int tid = threadIdx.x;
    for (int idx = tid; idx < 32 * 64; idx += 256) {
        int mm = idx >> 6, k = idx & 63;
        s_w1t[k * 32 + mm] = W1[idx];
    }
    if (tid < 8 * 32) { int o = tid >> 5, k = tid & 31; s_w2t[k * 8 + o] = W2[tid]; }
    if (tid < 32) s_b1[tid] = b1[tid];
    if (tid < 8)  s_b2[tid] = b2[tid];
    __syncthreads();

    const int bl = tid >> 5;
    const int mm = tid & 31;
    const int gb = blockIdx.x * 8 + bl;

    const float* hf = g_h + (size_t)gb * H2;
    const float* hb = g_h + (size_t)(BATCH + gb) * H2;

    float acc = s_b1[mm];
#pragma unroll
    for (int k = 0; k < 64; ++k)
        acc = fmaf(s_w1t[k * 32 + mm], hf[k] + hb[k], acc);
    s_m1[bl * 32 + mm] = acc;
    __syncthreads();

    if (mm < 8) {
        float a2 = s_b2[mm];
#pragma unroll
        for (int k = 0; k < 32; ++k)
            a2 = fmaf(s_w2t[k * 8 + mm], s_m1[bl * 32 + k], a2);
        out[(size_t)gb * 8 + mm] = a2;
    }
}

// ---------------------------------------------------------------------------
// Launch
// ---------------------------------------------------------------------------
extern "C" void kernel_launch(void* const* d_in, const int* in_sizes, int n_in,
                              void* d_out, int out_size) {
    const float* traj   = (const float*)d_in[0];
    const float* w_ih1  = (const float*)d_in[1];
    const float* w_hh1  = (const float*)d_in[2];
    const float* b_ih1  = (const float*)d_in[3];
    const float* b_hh1  = (const float*)d_in[4];
    const float* w_ih2f = (const float*)d_in[5];
    const float* w_hh2f = (const float*)d_in[6];
    const float* b_ih2f = (const float*)d_in[7];
    const float* b_hh2f = (const float*)d_in[8];
    const float* w_ih2b = (const float*)d_in[9];
    const float* w_hh2b = (const float*)d_in[10];
    const float* b_ih2b = (const float*)d_in[11];
    const float* b_hh2b = (const float*)d_in[12];
    const float* W1     = (const float*)d_in[13];
    const float* b1     = (const float*)d_in[14];
    const float* W2     = (const float*)d_in[15];
    const float* b2     = (const float*)d_in[16];

    cudaFuncSetAttribute(gru2_kernel,
                         cudaFuncAttributeMaxDynamicSharedMemorySize, SM2_TOTAL);

    gru1_kernel<<<BATCH / 16, 256>>>(traj, w_ih1, w_hh1, b_ih1, b_hh1);

    dim3 grid2(BATCH / 32, 2);   // (128, 2) = 256 CTAs -> 2 per SM
    gru2_kernel<<<grid2, 256, SM2_TOTAL>>>(w_ih2f, w_hh2f, b_ih2f, b_hh2f,
                                           w_ih2b, w_hh2b, b_ih2b, b_hh2b);

    mlp_kernel<<<BATCH / 8, 256>>>(W1, b1, W2, b2, (float*)d_out);
}

// round 14
// speedup vs baseline: 1.0167x; 1.0167x over previous
#include <cuda_runtime.h>
#include <cuda_fp16.h>
#include <cstdint>

#define TT    256
#define BATCH 4096
#define H1    16
#define H2    64

// ---------------------------------------------------------------------------
// Scratch
// ---------------------------------------------------------------------------
__device__ float g_out1[(size_t)TT * BATCH * H1];   // layer-1 outputs [T][B][16]
__device__ float g_h[2 * (size_t)BATCH * H2];       // final hidden per dir

// ---------------------------------------------------------------------------
// MUFU activations (EX2+RCP)
// ---------------------------------------------------------------------------
__device__ __forceinline__ float sig_mufu(float x) {
    return __fdividef(1.0f, 1.0f + __expf(-x));
}
__device__ __forceinline__ float tanh_mufu(float x) {
    return fmaf(2.0f, __fdividef(1.0f, 1.0f + __expf(-2.0f * x)), -1.0f);
}

__device__ __forceinline__ uint32_t smem_u32(const void* p) {
    uint32_t a;
    asm("{ .reg .u64 t; cvta.to.shared.u64 t, %1; cvt.u32.u64 %0, t; }" : "=r"(a) : "l"(p));
    return a;
}

#define LDSM_X4(r0, r1, r2, r3, addr) \
    asm volatile("ldmatrix.sync.aligned.m8n8.x4.shared.b16 {%0,%1,%2,%3}, [%4];" \
        : "=r"(r0), "=r"(r1), "=r"(r2), "=r"(r3) : "r"(addr))

#define MMA_F16(d, a0, a1, a2, a3, bb0, bb1) \
    asm volatile("mma.sync.aligned.m16n8k16.row.col.f32.f16.f16.f32 " \
        "{%0,%1,%2,%3}, {%4,%5,%6,%7}, {%8,%9}, {%0,%1,%2,%3};" \
        : "+f"((d)[0]), "+f"((d)[1]), "+f"((d)[2]), "+f"((d)[3]) \
        : "r"(a0), "r"(a1), "r"(a2), "r"(a3), "r"(bb0), "r"(bb1))

#define BAR_TEAM(id) \
    asm volatile("bar.sync %0, 64;" :: "r"(id) : "memory")

// fp16 split: v = hi + lo
__device__ __forceinline__ void f16_split(float v, unsigned short& hi, unsigned short& lo) {
    __half h = __float2half_rn(v);
    float rem = v - __half2float(h);
    __half l = __float2half_rn(rem);
    hi = __half_as_ushort(h);
    lo = __half_as_ushort(l);
}
__device__ __forceinline__ uint32_t f16_pair(float a, float b, uint32_t& lop) {
    unsigned short ha, la, hb, lb;
    f16_split(a, ha, la);
    f16_split(b, hb, lb);
    lop = (uint32_t)la | ((uint32_t)lb << 16);
    return (uint32_t)ha | ((uint32_t)hb << 16);
}

// ---------------------------------------------------------------------------
// Layer 2 (HMMA, fp16 3-term split): A [64 x 160] double-buffered, B [192 x 160].
//   A: [0:64) h_hi | [64:128) h_lo | [128:144) x_hi | [144:160) x_lo
//   B: [0:64) Whh_hi | [64:128) Whh_lo | [128:144) Wih_hi | [144:160) Wih_lo
// 256 threads = 4 TEAMS of 2 warps.  Team T owns rows [16T, 16T+16) — an
// independent recurrence.  In-loop sync is a per-team named barrier, so teams
// drift out of phase and tensor/MUFU phases of different teams overlap on
// each SMSP (R12/R13 showed a CTA-wide barrier convoy serializes the pipes).
// Warp within team: jh = wid&1 -> gate slice G0 = jh*32 (R12's proven layout).
// grid (64, 2) -> 1 CTA/SM.
// ---------------------------------------------------------------------------
#define AROW   336
#define SM_A0  0
#define SM_A1  21504                 // 64*336
#define SM_B   43008
#define SM2_TOTAL (43008 + 192 * 336)    // 107520

__global__ void __launch_bounds__(256)
gru2_kernel(const float* __restrict__ w_ihf, const float* __restrict__ w_hhf,
            const float* __restrict__ b_ihf, const float* __restrict__ b_hhf,
            const float* __restrict__ w_ihb, const float* __restrict__ w_hhb,
            const float* __restrict__ b_ihb, const float* __restrict__ b_hhb) {
    extern __shared__ char sm[];
    const uint32_t smb = smem_u32(sm);
    const int tid = threadIdx.x;
    const int wid = tid >> 5;
    const int lane = tid & 31;
    const int dir = blockIdx.y;
    const int b0 = blockIdx.x * 64;

    const float* w_ih = dir ? w_ihb : w_ihf;
    const float* w_hh = dir ? w_hhb : w_hhf;
    const float* b_ih = dir ? b_ihb : b_ihf;
    const float* b_hh = dir ? b_hhb : b_hhf;

    // ---- build B ----
    for (int idx = tid; idx < 192 * 64; idx += 256) {
        int g = idx >> 6, k = idx & 63;
        unsigned short hi, lo;
        f16_split(w_hh[idx], hi, lo);
        unsigned short* row = (unsigned short*)(sm + SM_B + g * AROW);
        row[k] = hi; row[64 + k] = lo;
    }
    for (int idx = tid; idx < 192 * 16; idx += 256) {
        int g = idx >> 4, k = idx & 15;
        unsigned short hi, lo;
        f16_split(w_ih[idx], hi, lo);
        unsigned short* row = (unsigned short*)(sm + SM_B + g * AROW);
        row[128 + k] = hi; row[144 + k] = lo;
    }
    for (int g = tid; g < 192; g += 256)
        *(uint4*)(sm + SM_B + g * AROW + 320) = make_uint4(0, 0, 0, 0);

    // ---- zero A buf0 (h(0)=0) ----
    for (int idx = tid; idx < 64 * (AROW / 16); idx += 256)
        ((uint4*)(sm + SM_A0))[idx] = make_uint4(0, 0, 0, 0);
    __syncthreads();

    // ---- stage x(t0): thread -> (row = tid>>2 in own team's range, 4 cols) ----
    const int xrow = tid >> 2;          // 0..63 (row xrow's team == this thread's team)
    const int xq   = (tid & 3) * 4;     // 0,4,8,12
    {
        int t0 = dir ? (TT - 1) : 0;
        float4 xv = *(const float4*)(g_out1 + ((size_t)t0 * BATCH + b0 + xrow) * 16 + xq);
        uint32_t l0, l1;
        uint32_t h0 = f16_pair(xv.x, xv.y, l0);
        uint32_t h1 = f16_pair(xv.z, xv.w, l1);
        char* ar = sm + SM_A0 + xrow * AROW;
        *(uint2*)(ar + 256 + 2 * xq) = make_uint2(h0, h1);
        *(uint2*)(ar + 288 + 2 * xq) = make_uint2(l0, l1);
    }

    // ---- team / warp / lane constants ----
    const int team = wid >> 1;          // 0..3, owns rows [team*16, +16)
    const int barid = 1 + team;
    const int jh = wid & 1;             // gate half
    const int G0 = jh * 32;             // j in [G0, G0+32)
    const int lrow = lane & 7;
    const int grp  = lane >> 3;
    const uint32_t aRowOff = (uint32_t)(team * 16 + lrow + ((grp & 1) << 3)) * AROW
                           + (uint32_t)((grp >> 1) << 4);
    const uint32_t bOff = (uint32_t)(lrow + ((grp >> 1) << 3)) * AROW
                        + (uint32_t)((grp & 1) << 4);
    const uint32_t bBase = smb + SM_B + bOff;

    // biases -> registers (d-accumulator init values)
    const int cj = 2 * (lane & 3);
    float2 br[4], bz[4], bhn[4], bxn[4];
#pragma unroll
    for (int o = 0; o < 4; ++o) {
        int j = G0 + 8 * o + cj;
        br[o]  = make_float2(b_ih[j] + b_hh[j],           b_ih[j + 1] + b_hh[j + 1]);
        bz[o]  = make_float2(b_ih[64 + j] + b_hh[64 + j], b_ih[65 + j] + b_hh[65 + j]);
        bhn[o] = make_float2(b_hh[128 + j], b_hh[129 + j]);
        bxn[o] = make_float2(b_ih[128 + j], b_ih[129 + j]);
    }

    float h[16];
#pragma unroll
    for (int i = 0; i < 16; ++i) h[i] = 0.0f;

    __syncthreads();   // B + A0 + x0 visible to all; teams independent hereafter

    const int row0 = team * 16 + (lane >> 2);
    const size_t xg_base = (size_t)(b0 + xrow) * 16 + xq;

    for (int step = 0; step < TT; ++step) {
        const uint32_t pa = smb + ((step & 1) ? SM_A1 : SM_A0);
        char* const   pn = sm + ((step & 1) ? SM_A0 : SM_A1);

        // prefetch x(t+1)
        float4 xv;
        const bool do_x = (step + 1 < TT);
        if (do_x) {
            int tn = dir ? (TT - 2 - step) : (step + 1);
            xv = *(const float4*)(g_out1 + (size_t)tn * BATCH * 16 + xg_base);
        }

        // ---- A fragments (10 LDSM) ----
        uint32_t ah[4][4], al[4][4], axh[4], axl[4];
#pragma unroll
        for (int kc = 0; kc < 4; ++kc)
            LDSM_X4(ah[kc][0], ah[kc][1], ah[kc][2], ah[kc][3], pa + aRowOff + kc * 32);
#pragma unroll
        for (int kc = 0; kc < 4; ++kc)
            LDSM_X4(al[kc][0], al[kc][1], al[kc][2], al[kc][3], pa + aRowOff + 128 + kc * 32);
        LDSM_X4(axh[0], axh[1], axh[2], axh[3], pa + aRowOff + 256);
        LDSM_X4(axl[0], axl[1], axl[2], axl[3], pa + aRowOff + 288);

        // d accumulators initialized with biases:
        // d[0..3]=r, d[4..7]=z, d[8..11]=hn, d[12..15]=xn  (o = nb*2 + n8)
        float d[16][4];
#pragma unroll
        for (int o = 0; o < 4; ++o) {
            d[o][0]      = br[o].x;  d[o][1]      = br[o].y;
            d[o][2]      = br[o].x;  d[o][3]      = br[o].y;
            d[4 + o][0]  = bz[o].x;  d[4 + o][1]  = bz[o].y;
            d[4 + o][2]  = bz[o].x;  d[4 + o][3]  = bz[o].y;
            d[8 + o][0]  = bhn[o].x; d[8 + o][1]  = bhn[o].y;
            d[8 + o][2]  = bhn[o].x; d[8 + o][3]  = bhn[o].y;
            d[12 + o][0] = bxn[o].x; d[12 + o][1] = bxn[o].y;
            d[12 + o][2] = bxn[o].x; d[12 + o][3] = bxn[o].y;
        }

        // ---- MMA phase (R12 structure) ----
#pragma unroll
        for (int sec = 0; sec < 3; ++sec) {
#pragma unroll
            for (int nb = 0; nb < 2; ++nb) {
                const uint32_t rowb = bBase + (uint32_t)(sec * 64 + G0 + nb * 16) * AROW;
                const int iH = (sec < 2 ? sec * 4 : 8) + nb * 2;
                const int iX = (sec < 2 ? sec * 4 : 12) + nb * 2;
                uint32_t q0, q1, q2, q3;
#pragma unroll
                for (int kc = 0; kc < 4; ++kc) {
                    LDSM_X4(q0, q1, q2, q3, rowb + kc * 32);
                    MMA_F16(d[iH],     ah[kc][0], ah[kc][1], ah[kc][2], ah[kc][3], q0, q1);
                    MMA_F16(d[iH + 1], ah[kc][0], ah[kc][1], ah[kc][2], ah[kc][3], q2, q3);
                    MMA_F16(d[iH],     al[kc][0], al[kc][1], al[kc][2], al[kc][3], q0, q1);
                    MMA_F16(d[iH + 1], al[kc][0], al[kc][1], al[kc][2], al[kc][3], q2, q3);
                    LDSM_X4(q0, q1, q2, q3, rowb + 128 + kc * 32);
                    MMA_F16(d[iH],     ah[kc][0], ah[kc][1], ah[kc][2], ah[kc][3], q0, q1);
                    MMA_F16(d[iH + 1], ah[kc][0], ah[kc][1], ah[kc][2], ah[kc][3], q2, q3);
                }
                LDSM_X4(q0, q1, q2, q3, rowb + 256);
                MMA_F16(d[iX],     axh[0], axh[1], axh[2], axh[3], q0, q1);
                MMA_F16(d[iX + 1], axh[0], axh[1], axh[2], axh[3], q2, q3);
                MMA_F16(d[iX],     axl[0], axl[1], axl[2], axl[3], q0, q1);
                MMA_F16(d[iX + 1], axl[0], axl[1], axl[2], axl[3], q2, q3);
                LDSM_X4(q0, q1, q2, q3, rowb + 288);
                MMA_F16(d[iX],     axh[0], axh[1], axh[2], axh[3], q0, q1);
                MMA_F16(d[iX + 1], axh[0], axh[1], axh[2], axh[3], q2, q3);
            }
        }

        // ---- epilogue (MUFU) + h writeback to next A buffer ----
#pragma unroll
        for (int o = 0; o < 4; ++o) {
#pragma unroll
            for (int e = 0; e < 4; ++e) {
                float rg = sig_mufu(d[o][e]);
                float zg = sig_mufu(d[4 + o][e]);
                float nn = tanh_mufu(fmaf(rg, d[8 + o][e], d[12 + o][e]));
                const int hi = o * 4 + e;
                h[hi] = fmaf(zg, h[hi] - nn, nn);
            }
#pragma unroll
            for (int rsel = 0; rsel < 2; ++rsel) {
                const int e0 = rsel * 2;
                uint32_t LP, HP = f16_pair(h[o * 4 + e0], h[o * 4 + e0 + 1], LP);
                char* ar = pn + (row0 + rsel * 8) * AROW;
                const int j = G0 + 8 * o + cj;
                *(uint32_t*)(ar + 2 * j)       = HP;   // h_hi
                *(uint32_t*)(ar + 128 + 2 * j) = LP;   // h_lo (col 64)
            }
        }

        // stage x(t+1) (own team's rows)
        if (do_x) {
            uint32_t l0, l1;
            uint32_t h0 = f16_pair(xv.x, xv.y, l0);
            uint32_t h1 = f16_pair(xv.z, xv.w, l1);
            char* ar = pn + xrow * AROW;
            *(uint2*)(ar + 256 + 2 * xq) = make_uint2(h0, h1);
            *(uint2*)(ar + 288 + 2 * xq) = make_uint2(l0, l1);
        }
        BAR_TEAM(barid);   // only the 2 warps of this team sync
    }

    // final hidden -> gmem
#pragma unroll
    for (int o = 0; o < 4; ++o) {
#pragma unroll
        for (int rsel = 0; rsel < 2; ++rsel) {
            const int j = G0 + 8 * o + cj;
            float* hp = g_h + ((size_t)dir * BATCH + b0 + row0 + rsel * 8) * H2 + j;
            *(float2*)hp = make_float2(h[o * 4 + rsel * 2], h[o * 4 + rsel * 2 + 1]);
        }
    }
}

// ---------------------------------------------------------------------------
// Layer 1: GRU(2 -> 16), barrier-free warp-shuffle, MUFU activations.
// ---------------------------------------------------------------------------
__global__ void __launch_bounds__(256)
gru1_kernel(const float* __restrict__ traj,
            const float* __restrict__ w_ih1,
            const float* __restrict__ w_hh1,
            const float* __restrict__ b_ih1,
            const float* __restrict__ b_hh1) {
    const int tid  = threadIdx.x;
    const int wid  = tid >> 5;
    const int lane = tid & 31;
    const int half = lane >> 4;
    const int j    = lane & 15;
    const int el   = (blockIdx.x * 8 + wid) * 2 + half;

    float whr[16], whz[16], whn[16];
#pragma unroll
    for (int k = 0; k < 16; ++k) {
        whr[k] = w_hh1[(j)      * 16 + k];
        whz[k] = w_hh1[(16 + j) * 16 + k];
        whn[k] = w_hh1[(32 + j) * 16 + k];
    }
    const float wxr0 = w_ih1[j * 2 + 0],        wxr1 = w_ih1[j * 2 + 1];
    const float wxz0 = w_ih1[(16 + j) * 2 + 0], wxz1 = w_ih1[(16 + j) * 2 + 1];
    const float wxn0 = w_ih1[(32 + j) * 2 + 0], wxn1 = w_ih1[(32 + j) * 2 + 1];
    const float br  = b_ih1[j]      + b_hh1[j];
    const float bz  = b_ih1[16 + j] + b_hh1[16 + j];
    const float bxn = b_ih1[32 + j];
    const float bhn = b_hh1[32 + j];

    const float2* xp = (const float2*)(traj + (size_t)el * TT * 2);
    float* op = g_out1 + (size_t)el * 16 + j;
    const int sbase = half << 4;

    float h = 0.0f;
    float2 xv = xp[0];
    for (int t = 0; t < TT; ++t) {
        float x0 = xv.x, x1 = xv.y;
        if (t + 1 < TT) xv = xp[t + 1];

        float ar  = fmaf(wxr1, x1, fmaf(wxr0, x0, br));
        float az  = fmaf(wxz1, x1, fmaf(wxz0, x0, bz));
        float axn = fmaf(wxn1, x1, fmaf(wxn0, x0, bxn));
        float ahn = bhn;
#pragma unroll
        for (int k = 0; k < 16; ++k) {
            float hk = __shfl_sync(0xFFFFFFFFu, h, sbase + k);
            ar  = fmaf(whr[k], hk, ar);
            az  = fmaf(whz[k], hk, az);
            ahn = fmaf(whn[k], hk, ahn);
        }
        float r = sig_mufu(ar);
        float z = sig_mufu(az);
        float n = tanh_mufu(fmaf(r, ahn, axn));
        h = fmaf(z, h - n, n);
        op[(size_t)t * BATCH * 16] = h;
    }
}

// ---------------------------------------------------------------------------
// MLP
// ---------------------------------------------------------------------------
__global__ void mlp_kernel(const float* __restrict__ W1, const float* __restrict__ b1,
                           const float* __restrict__ W2, const float* __restrict__ b2,
                           float* __restrict__ out) {
    __shared__ float s_w1t[64 * 32];
    __shared__ float s_w2t[32 * 8];
    __shared__ float s_b1[32];
    __shared__ float s_b2[8];
    __shared__ float s_m1[8 * 32];

    const int tid = threadIdx.x;
    for (int idx = tid; idx < 32 * 64; idx += 256) {
        int mm = idx >> 6, k = idx & 63;
        s_w1t[k * 32 + mm] = W1[idx];
    }
    if (tid < 8 * 32) { int o = tid >> 5, k = tid & 31; s_w2t[k * 8 + o] = W2[tid]; }
    if (tid < 32) s_b1[tid] = b1[tid];
    if (tid < 8)  s_b2[tid] = b2[tid];
    __syncthreads();

    const int bl = tid >> 5;
    const int mm = tid & 31;
    const int gb = blockIdx.x * 8 + bl;

    const float* hf = g_h + (size_t)gb * H2;
    const float* hb = g_h + (size_t)(BATCH + gb) * H2;

    float acc = s_b1[mm];
#pragma unroll
    for (int k = 0; k < 64; ++k)
        acc = fmaf(s_w1t[k * 32 + mm], hf[k] + hb[k], acc);
    s_m1[bl * 32 + mm] = acc;
    __syncthreads();

    if (mm < 8) {
        float a2 = s_b2[mm];
#pragma unroll
        for (int k = 0; k < 32; ++k)
            a2 = fmaf(s_w2t[k * 8 + mm], s_m1[bl * 32 + k], a2);
        out[(size_t)gb * 8 + mm] = a2;
    }
}

// ---------------------------------------------------------------------------
// Launch
// ---------------------------------------------------------------------------
extern "C" void kernel_launch(void* const* d_in, const int* in_sizes, int n_in,
                              void* d_out, int out_size) {
    const float* traj   = (const float*)d_in[0];
    const float* w_ih1  = (const float*)d_in[1];
    const float* w_hh1  = (const float*)d_in[2];
    const float* b_ih1  = (const float*)d_in[3];
    const float* b_hh1  = (const float*)d_in[4];
    const float* w_ih2f = (const float*)d_in[5];
    const float* w_hh2f = (const float*)d_in[6];
    const float* b_ih2f = (const float*)d_in[7];
    const float* b_hh2f = (const float*)d_in[8];
    const float* w_ih2b = (const float*)d_in[9];
    const float* w_hh2b = (const float*)d_in[10];
    const float* b_ih2b = (const float*)d_in[11];
    const float* b_hh2b = (const float*)d_in[12];
    const float* W1     = (const float*)d_in[13];
    const float* b1     = (const float*)d_in[14];
    const float* W2     = (const float*)d_in[15];
    const float* b2     = (const float*)d_in[16];

    cudaFuncSetAttribute(gru2_kernel,
                         cudaFuncAttributeMaxDynamicSharedMemorySize, SM2_TOTAL);

    gru1_kernel<<<BATCH / 16, 256>>>(traj, w_ih1, w_hh1, b_ih1, b_hh1);

    dim3 grid2(BATCH / 64, 2);   // (64, 2) = 128 CTAs -> 1 per SM
    gru2_kernel<<<grid2, 256, SM2_TOTAL>>>(w_ih2f, w_hh2f, b_ih2f, b_hh2f,
                                           w_ih2b, w_hh2b, b_ih2b, b_hh2b);

    mlp_kernel<<<BATCH / 8, 256>>>(W1, b1, W2, b2, (float*)d_out);
}

// round 15
// speedup vs baseline: 1.0951x; 1.0771x over previous
#include <cuda_runtime.h>
#include <cuda_fp16.h>
#include <cstdint>

#define TT    256
#define BATCH 4096
#define H1    16
#define H2    64

// ---------------------------------------------------------------------------
// Scratch
// ---------------------------------------------------------------------------
__device__ float g_out1[(size_t)TT * BATCH * H1];   // layer-1 outputs [T][B][16]
__device__ float g_h[2 * (size_t)BATCH * H2];       // final hidden per dir

// ---------------------------------------------------------------------------
// MUFU activations (EX2+RCP)
// ---------------------------------------------------------------------------
__device__ __forceinline__ float sig_mufu(float x) {
    return __fdividef(1.0f, 1.0f + __expf(-x));
}
__device__ __forceinline__ float tanh_mufu(float x) {
    return fmaf(2.0f, __fdividef(1.0f, 1.0f + __expf(-2.0f * x)), -1.0f);
}

__device__ __forceinline__ uint32_t smem_u32(const void* p) {
    uint32_t a;
    asm("{ .reg .u64 t; cvta.to.shared.u64 t, %1; cvt.u32.u64 %0, t; }" : "=r"(a) : "l"(p));
    return a;
}

#define LDSM_X4(r0, r1, r2, r3, addr) \
    asm volatile("ldmatrix.sync.aligned.m8n8.x4.shared.b16 {%0,%1,%2,%3}, [%4];" \
        : "=r"(r0), "=r"(r1), "=r"(r2), "=r"(r3) : "r"(addr))

#define MMA_F16(d, a0, a1, a2, a3, bb0, bb1) \
    asm volatile("mma.sync.aligned.m16n8k16.row.col.f32.f16.f16.f32 " \
        "{%0,%1,%2,%3}, {%4,%5,%6,%7}, {%8,%9}, {%0,%1,%2,%3};" \
        : "+f"((d)[0]), "+f"((d)[1]), "+f"((d)[2]), "+f"((d)[3]) \
        : "r"(a0), "r"(a1), "r"(a2), "r"(a3), "r"(bb0), "r"(bb1))

// fp16 split: v = hi + lo
__device__ __forceinline__ void f16_split(float v, unsigned short& hi, unsigned short& lo) {
    __half h = __float2half_rn(v);
    float rem = v - __half2float(h);
    __half l = __float2half_rn(rem);
    hi = __half_as_ushort(h);
    lo = __half_as_ushort(l);
}
__device__ __forceinline__ uint32_t f16_pair(float a, float b, uint32_t& lop) {
    unsigned short ha, la, hb, lb;
    f16_split(a, ha, la);
    f16_split(b, hb, lb);
    lop = (uint32_t)la | ((uint32_t)lb << 16);
    return (uint32_t)ha | ((uint32_t)hb << 16);
}

// ---------------------------------------------------------------------------
// Layer 2 (HMMA, fp16 3-term split), B RESIDENT IN REGISTERS.
// A [16 x 160] double-buffered in smem; B [192 x 160] staged to smem once,
// then each warp loads its 16-gate slice of B into 120 registers and never
// touches B smem again (R12 spent 60 B-LDSM/warp/step on a CONSTANT matrix).
//   A: [0:64) h_hi | [64:128) h_lo | [128:144) x_hi | [144:160) x_lo
//   B: [0:64) Whh_hi | [64:128) Whh_lo | [128:144) Wih_hi | [144:160) Wih_lo
// CTA = 128 threads = 4 warps (warp jq owns gates [jq*16, +16)), M=16 rows.
// grid (256, 2), 2 CTAs/SM co-resident (proven better than teams in R12/R14).
// ---------------------------------------------------------------------------
#define AROW   336
#define SM_A0  0
#define SM_A1  5376                  // 16*336
#define SM_B   10752
#define SM2_TOTAL (10752 + 192 * 336)    // 75264

__global__ void __launch_bounds__(128, 2)
gru2_kernel(const float* __restrict__ w_ihf, const float* __restrict__ w_hhf,
            const float* __restrict__ b_ihf, const float* __restrict__ b_hhf,
            const float* __restrict__ w_ihb, const float* __restrict__ w_hhb,
            const float* __restrict__ b_ihb, const float* __restrict__ b_hhb) {
    extern __shared__ char sm[];
    const uint32_t smb = smem_u32(sm);
    const int tid = threadIdx.x;
    const int wid = tid >> 5;
    const int lane = tid & 31;
    const int dir = blockIdx.y;
    const int b0 = blockIdx.x * 16;

    const float* w_ih = dir ? w_ihb : w_ihf;
    const float* w_hh = dir ? w_hhb : w_hhf;
    const float* b_ih = dir ? b_ihb : b_ihf;
    const float* b_hh = dir ? b_hhb : b_hhf;

    // ---- build B in smem (staging for the one-time register load) ----
    for (int idx = tid; idx < 192 * 64; idx += 128) {
        int g = idx >> 6, k = idx & 63;
        unsigned short hi, lo;
        f16_split(w_hh[idx], hi, lo);
        unsigned short* row = (unsigned short*)(sm + SM_B + g * AROW);
        row[k] = hi; row[64 + k] = lo;
    }
    for (int idx = tid; idx < 192 * 16; idx += 128) {
        int g = idx >> 4, k = idx & 15;
        unsigned short hi, lo;
        f16_split(w_ih[idx], hi, lo);
        unsigned short* row = (unsigned short*)(sm + SM_B + g * AROW);
        row[128 + k] = hi; row[144 + k] = lo;
    }
    for (int g = tid; g < 192; g += 128)
        *(uint4*)(sm + SM_B + g * AROW + 320) = make_uint4(0, 0, 0, 0);

    // ---- zero A buf0 (h(0)=0) ----
    for (int idx = tid; idx < 16 * (AROW / 16); idx += 128)
        ((uint4*)(sm + SM_A0))[idx] = make_uint4(0, 0, 0, 0);
    __syncthreads();

    // ---- per-warp / per-lane constants ----
    const int jq = wid;                 // gate slice [jq*16, jq*16+16)
    const int lrow = lane & 7;
    const int grp  = lane >> 3;
    const uint32_t aRowOff = (uint32_t)(lrow + ((grp & 1) << 3)) * AROW
                           + (uint32_t)((grp >> 1) << 4);
    const uint32_t bOff = (uint32_t)(lrow + ((grp >> 1) << 3)) * AROW
                        + (uint32_t)((grp & 1) << 4);
    const uint32_t bBase = smb + SM_B + bOff;

    // ---- load B fragments into registers (once; 30 LDSM total) ----
    uint32_t Bhh[3][4][4];   // [sec][kc][frag]  Whh_hi
    uint32_t Bhl[3][4][4];   //                  Whh_lo
    uint32_t Bxh[3][4];      // Wih_hi
    uint32_t Bxl[3][4];      // Wih_lo
#pragma unroll
    for (int sec = 0; sec < 3; ++sec) {
        const uint32_t rowb = bBase + (uint32_t)(sec * 64 + jq * 16) * AROW;
#pragma unroll
        for (int kc = 0; kc < 4; ++kc)
            LDSM_X4(Bhh[sec][kc][0], Bhh[sec][kc][1], Bhh[sec][kc][2], Bhh[sec][kc][3],
                    rowb + kc * 32);
#pragma unroll
        for (int kc = 0; kc < 4; ++kc)
            LDSM_X4(Bhl[sec][kc][0], Bhl[sec][kc][1], Bhl[sec][kc][2], Bhl[sec][kc][3],
                    rowb + 128 + kc * 32);
        LDSM_X4(Bxh[sec][0], Bxh[sec][1], Bxh[sec][2], Bxh[sec][3], rowb + 256);
        LDSM_X4(Bxl[sec][0], Bxl[sec][1], Bxl[sec][2], Bxl[sec][3], rowb + 288);
    }

    // ---- stage x(t0): 128 threads = 16 rows x 8 col-pairs ----
    const int xrow = tid >> 3;          // 0..15
    const int xc2  = (tid & 7) * 2;     // 0,2,...,14
    {
        int t0 = dir ? (TT - 1) : 0;
        float2 xv = *(const float2*)(g_out1 + ((size_t)t0 * BATCH + b0 + xrow) * 16 + xc2);
        uint32_t LP, HP = f16_pair(xv.x, xv.y, LP);
        char* ar = sm + SM_A0 + xrow * AROW;
        *(uint32_t*)(ar + 256 + 2 * xc2) = HP;
        *(uint32_t*)(ar + 288 + 2 * xc2) = LP;
    }

    // biases (d-accumulator init values)
    const int cj = 2 * (lane & 3);
    float2 br[2], bz[2], bhn[2], bxn[2];
#pragma unroll
    for (int nbh = 0; nbh < 2; ++nbh) {
        int j = jq * 16 + nbh * 8 + cj;
        br[nbh]  = make_float2(b_ih[j] + b_hh[j],           b_ih[j + 1] + b_hh[j + 1]);
        bz[nbh]  = make_float2(b_ih[64 + j] + b_hh[64 + j], b_ih[65 + j] + b_hh[65 + j]);
        bhn[nbh] = make_float2(b_hh[128 + j], b_hh[129 + j]);
        bxn[nbh] = make_float2(b_ih[128 + j], b_ih[129 + j]);
    }

    float h[8];
#pragma unroll
    for (int i = 0; i < 8; ++i) h[i] = 0.0f;

    __syncthreads();   // x(t0) + A0 zero visible

    const int row0 = lane >> 2;
    const size_t xg_base = (size_t)(b0 + xrow) * 16 + xc2;

    for (int step = 0; step < TT; ++step) {
        const uint32_t pa = smb + ((step & 1) ? SM_A1 : SM_A0);
        char* const   pn = sm + ((step & 1) ? SM_A0 : SM_A1);

        // prefetch x(t+1)
        float2 xv;
        const bool do_x = (step + 1 < TT);
        if (do_x) {
            int tn = dir ? (TT - 2 - step) : (step + 1);
            xv = *(const float2*)(g_out1 + (size_t)tn * BATCH * 16 + xg_base);
        }

        // ---- A fragments (10 LDSM; the ONLY smem loads in the loop) ----
        uint32_t ah[4][4], al[4][4], axh[4], axl[4];
#pragma unroll
        for (int kc = 0; kc < 4; ++kc)
            LDSM_X4(ah[kc][0], ah[kc][1], ah[kc][2], ah[kc][3], pa + aRowOff + kc * 32);
#pragma unroll
        for (int kc = 0; kc < 4; ++kc)
            LDSM_X4(al[kc][0], al[kc][1], al[kc][2], al[kc][3], pa + aRowOff + 128 + kc * 32);
        LDSM_X4(axh[0], axh[1], axh[2], axh[3], pa + aRowOff + 256);
        LDSM_X4(axl[0], axl[1], axl[2], axl[3], pa + aRowOff + 288);

        // d accumulators initialized with biases:
        // d[0..1]=r, d[2..3]=z, d[4..5]=hn, d[6..7]=xn  (index = type*2 + nbh)
        float d[8][4];
#pragma unroll
        for (int nbh = 0; nbh < 2; ++nbh) {
            d[0 + nbh][0] = br[nbh].x;  d[0 + nbh][1] = br[nbh].y;
            d[0 + nbh][2] = br[nbh].x;  d[0 + nbh][3] = br[nbh].y;
            d[2 + nbh][0] = bz[nbh].x;  d[2 + nbh][1] = bz[nbh].y;
            d[2 + nbh][2] = bz[nbh].x;  d[2 + nbh][3] = bz[nbh].y;
            d[4 + nbh][0] = bhn[nbh].x; d[4 + nbh][1] = bhn[nbh].y;
            d[4 + nbh][2] = bhn[nbh].x; d[4 + nbh][3] = bhn[nbh].y;
            d[6 + nbh][0] = bxn[nbh].x; d[6 + nbh][1] = bxn[nbh].y;
            d[6 + nbh][2] = bxn[nbh].x; d[6 + nbh][3] = bxn[nbh].y;
        }

        // ---- MMA phase: 90 HMMA, all B operands from registers ----
#pragma unroll
        for (int sec = 0; sec < 3; ++sec) {
            const int iH = (sec < 2) ? sec * 2 : 4;
            const int iX = (sec < 2) ? sec * 2 : 6;
#pragma unroll
            for (int kc = 0; kc < 4; ++kc) {
                MMA_F16(d[iH],     ah[kc][0], ah[kc][1], ah[kc][2], ah[kc][3],
                        Bhh[sec][kc][0], Bhh[sec][kc][1]);
                MMA_F16(d[iH + 1], ah[kc][0], ah[kc][1], ah[kc][2], ah[kc][3],
                        Bhh[sec][kc][2], Bhh[sec][kc][3]);
                MMA_F16(d[iH],     al[kc][0], al[kc][1], al[kc][2], al[kc][3],
                        Bhh[sec][kc][0], Bhh[sec][kc][1]);
                MMA_F16(d[iH + 1], al[kc][0], al[kc][1], al[kc][2], al[kc][3],
                        Bhh[sec][kc][2], Bhh[sec][kc][3]);
                MMA_F16(d[iH],     ah[kc][0], ah[kc][1], ah[kc][2], ah[kc][3],
                        Bhl[sec][kc][0], Bhl[sec][kc][1]);
                MMA_F16(d[iH + 1], ah[kc][0], ah[kc][1], ah[kc][2], ah[kc][3],
                        Bhl[sec][kc][2], Bhl[sec][kc][3]);
            }
            MMA_F16(d[iX],     axh[0], axh[1], axh[2], axh[3], Bxh[sec][0], Bxh[sec][1]);
            MMA_F16(d[iX + 1], axh[0], axh[1], axh[2], axh[3], Bxh[sec][2], Bxh[sec][3]);
            MMA_F16(d[iX],     axl[0], axl[1], axl[2], axl[3], Bxh[sec][0], Bxh[sec][1]);
            MMA_F16(d[iX + 1], axl[0], axl[1], axl[2], axl[3], Bxh[sec][2], Bxh[sec][3]);
            MMA_F16(d[iX],     axh[0], axh[1], axh[2], axh[3], Bxl[sec][0], Bxl[sec][1]);
            MMA_F16(d[iX + 1], axh[0], axh[1], axh[2], axh[3], Bxl[sec][2], Bxl[sec][3]);
        }

        // No mid-step barrier (pn's previous readers finished before the
        // previous end-of-step barrier).

        // ---- epilogue (MUFU) + h writeback to next A buffer ----
#pragma unroll
        for (int nbh = 0; nbh < 2; ++nbh) {
#pragma unroll
            for (int e = 0; e < 4; ++e) {
                float rg = sig_mufu(d[0 + nbh][e]);
                float zg = sig_mufu(d[2 + nbh][e]);
                float nn = tanh_mufu(fmaf(rg, d[4 + nbh][e], d[6 + nbh][e]));
                const int hi = nbh * 4 + e;
                h[hi] = fmaf(zg, h[hi] - nn, nn);
            }
#pragma unroll
            for (int rsel = 0; rsel < 2; ++rsel) {
                const int e0 = rsel * 2;
                uint32_t LP, HP = f16_pair(h[nbh * 4 + e0], h[nbh * 4 + e0 + 1], LP);
                char* ar = pn + (row0 + rsel * 8) * AROW;
                const int j = jq * 16 + nbh * 8 + cj;
                *(uint32_t*)(ar + 2 * j)       = HP;   // h_hi
                *(uint32_t*)(ar + 128 + 2 * j) = LP;   // h_lo (col 64)
            }
        }

        // stage x(t+1)
        if (do_x) {
            uint32_t LP, HP = f16_pair(xv.x, xv.y, LP);
            char* ar = pn + xrow * AROW;
            *(uint32_t*)(ar + 256 + 2 * xc2) = HP;
            *(uint32_t*)(ar + 288 + 2 * xc2) = LP;
        }
        __syncthreads();   // A(next) complete before next step's LDSMs
    }

    // final hidden -> gmem
#pragma unroll
    for (int nbh = 0; nbh < 2; ++nbh) {
#pragma unroll
        for (int rsel = 0; rsel < 2; ++rsel) {
            const int j = jq * 16 + nbh * 8 + cj;
            float* hp = g_h + ((size_t)dir * BATCH + b0 + row0 + rsel * 8) * H2 + j;
            *(float2*)hp = make_float2(h[nbh * 4 + rsel * 2], h[nbh * 4 + rsel * 2 + 1]);
        }
    }
}

// ---------------------------------------------------------------------------
// Layer 1: GRU(2 -> 16), barrier-free warp-shuffle, MUFU activations.
// ---------------------------------------------------------------------------
__global__ void __launch_bounds__(256)
gru1_kernel(const float* __restrict__ traj,
            const float* __restrict__ w_ih1,
            const float* __restrict__ w_hh1,
            const float* __restrict__ b_ih1,
            const float* __restrict__ b_hh1) {
    const int tid  = threadIdx.x;
    const int wid  = tid >> 5;
    const int lane = tid & 31;
    const int half = lane >> 4;
    const int j    = lane & 15;
    const int el   = (blockIdx.x * 8 + wid) * 2 + half;

    float whr[16], whz[16], whn[16];
#pragma unroll
    for (int k = 0; k < 16; ++k) {
        whr[k] = w_hh1[(j)      * 16 + k];
        whz[k] = w_hh1[(16 + j) * 16 + k];
        whn[k] = w_hh1[(32 + j) * 16 + k];
    }
    const float wxr0 = w_ih1[j * 2 + 0],        wxr1 = w_ih1[j * 2 + 1];
    const float wxz0 = w_ih1[(16 + j) * 2 + 0], wxz1 = w_ih1[(16 + j) * 2 + 1];
    const float wxn0 = w_ih1[(32 + j) * 2 + 0], wxn1 = w_ih1[(32 + j) * 2 + 1];
    const float br  = b_ih1[j]      + b_hh1[j];
    const float bz  = b_ih1[16 + j] + b_hh1[16 + j];
    const float bxn = b_ih1[32 + j];
    const float bhn = b_hh1[32 + j];

    const float2* xp = (const float2*)(traj + (size_t)el * TT * 2);
    float* op = g_out1 + (size_t)el * 16 + j;
    const int sbase = half << 4;

    float h = 0.0f;
    float2 xv = xp[0];
    for (int t = 0; t < TT; ++t) {
        float x0 = xv.x, x1 = xv.y;
        if (t + 1 < TT) xv = xp[t + 1];

        float ar  = fmaf(wxr1, x1, fmaf(wxr0, x0, br));
        float az  = fmaf(wxz1, x1, fmaf(wxz0, x0, bz));
        float axn = fmaf(wxn1, x1, fmaf(wxn0, x0, bxn));
        float ahn = bhn;
#pragma unroll
        for (int k = 0; k < 16; ++k) {
            float hk = __shfl_sync(0xFFFFFFFFu, h, sbase + k);
            ar  = fmaf(whr[k], hk, ar);
            az  = fmaf(whz[k], hk, az);
            ahn = fmaf(whn[k], hk, ahn);
        }
        float r = sig_mufu(ar);
        float z = sig_mufu(az);
        float n = tanh_mufu(fmaf(r, ahn, axn));
        h = fmaf(z, h - n, n);
        op[(size_t)t * BATCH * 16] = h;
    }
}

// ---------------------------------------------------------------------------
// MLP
// ---------------------------------------------------------------------------
__global__ void mlp_kernel(const float* __restrict__ W1, const float* __restrict__ b1,
                           const float* __restrict__ W2, const float* __restrict__ b2,
                           float* __restrict__ out) {
    __shared__ float s_w1t[64 * 32];
    __shared__ float s_w2t[32 * 8];
    __shared__ float s_b1[32];
    __shared__ float s_b2[8];
    __shared__ float s_m1[8 * 32];

    const int tid = threadIdx.x;
    for (int idx = tid; idx < 32 * 64; idx += 256) {
        int mm = idx >> 6, k = idx & 63;
        s_w1t[k * 32 + mm] = W1[idx];
    }
    if (tid < 8 * 32) { int o = tid >> 5, k = tid & 31; s_w2t[k * 8 + o] = W2[tid]; }
    if (tid < 32) s_b1[tid] = b1[tid];
    if (tid < 8)  s_b2[tid] = b2[tid];
    __syncthreads();

    const int bl = tid >> 5;
    const int mm = tid & 31;
    const int gb = blockIdx.x * 8 + bl;

    const float* hf = g_h + (size_t)gb * H2;
    const float* hb = g_h + (size_t)(BATCH + gb) * H2;

    float acc = s_b1[mm];
#pragma unroll
    for (int k = 0; k < 64; ++k)
        acc = fmaf(s_w1t[k * 32 + mm], hf[k] + hb[k], acc);
    s_m1[bl * 32 + mm] = acc;
    __syncthreads();

    if (mm < 8) {
        float a2 = s_b2[mm];
#pragma unroll
        for (int k = 0; k < 32; ++k)
            a2 = fmaf(s_w2t[k * 8 + mm], s_m1[bl * 32 + k], a2);
        out[(size_t)gb * 8 + mm] = a2;
    }
}

// ---------------------------------------------------------------------------
// Launch
// ---------------------------------------------------------------------------
extern "C" void kernel_launch(void* const* d_in, const int* in_sizes, int n_in,
                              void* d_out, int out_size) {
    const float* traj   = (const float*)d_in[0];
    const float* w_ih1  = (const float*)d_in[1];
    const float* w_hh1  = (const float*)d_in[2];
    const float* b_ih1  = (const float*)d_in[3];
    const float* b_hh1  = (const float*)d_in[4];
    const float* w_ih2f = (const float*)d_in[5];
    const float* w_hh2f = (const float*)d_in[6];
    const float* b_ih2f = (const float*)d_in[7];
    const float* b_hh2f = (const float*)d_in[8];
    const float* w_ih2b = (const float*)d_in[9];
    const float* w_hh2b = (const float*)d_in[10];
    const float* b_ih2b = (const float*)d_in[11];
    const float* b_hh2b = (const float*)d_in[12];
    const float* W1     = (const float*)d_in[13];
    const float* b1     = (const float*)d_in[14];
    const float* W2     = (const float*)d_in[15];
    const float* b2     = (const float*)d_in[16];

    cudaFuncSetAttribute(gru2_kernel,
                         cudaFuncAttributeMaxDynamicSharedMemorySize, SM2_TOTAL);

    gru1_kernel<<<BATCH / 16, 256>>>(traj, w_ih1, w_hh1, b_ih1, b_hh1);

    dim3 grid2(BATCH / 16, 2);   // (256, 2) = 512 CTAs -> 2 co-resident per SM
    gru2_kernel<<<grid2, 128, SM2_TOTAL>>>(w_ih2f, w_hh2f, b_ih2f, b_hh2f,
                                           w_ih2b, w_hh2b, b_ih2b, b_hh2b);

    mlp_kernel<<<BATCH / 8, 256>>>(W1, b1, W2, b2, (float*)d_out);
}